// round 14
// baseline (speedup 1.0000x reference)
#include <cuda_runtime.h>
#include <cuda_bf16.h>
#include <math.h>

#define T_  128
#define B_  128
#define I_  128
#define H_  512
#define W_  16
#define G4  2048
#define BH  65536
#define TB  16384
#define NCTA 148
#define INV_SQRT_DK 0.04419417382415922f

typedef __nv_bfloat16 bf16;

// ---------------- device scratch (static) -----------------------------------
__device__ __align__(16) float g_XWi[(size_t)TB * G4];   // x@Wi_perm + bia_perm (gate-interleaved cols)
__device__ __align__(16) float g_XQV[(size_t)TB * H_];   // x@(Wqx@WvT)
__device__ __align__(16) float g_WhWa[1024 * G4];        // fp32 [Wh ; Wv@Wa] (ORIG col layout)
__device__ __align__(16) float g_Wqv[H_ * H_];           // fp32 Wqh@WvT
__device__ __align__(16) float g_Wqxv[I_ * H_];          // fp32 Wqx@WvT
__device__ __align__(16) float g_WvT[H_ * H_];
__device__ __align__(16) float g_bia[G4];                // permuted
__device__ __align__(16) float g_bqv[H_];
__device__ __align__(16) float g_wqb[H_];
__device__ __align__(16) float g_u[I_];
__device__ float g_sbq;
__device__ __align__(16) float g_h[BH];
__device__ __align__(16) float g_c[BH];
__device__ __align__(16) float g_Cbuf[W_ * BH];
__device__ __align__(16) float g_Qp[8 * BH];
__device__ volatile unsigned g_flags[NCTA * 32];

// hi/lo bf16 split operands
__device__ __align__(16) bf16 g_xh[(size_t)TB * I_],  g_xl[(size_t)TB * I_];
__device__ __align__(16) bf16 g_Wih[I_ * G4],         g_Wil[I_ * G4];     // permuted cols
__device__ __align__(16) bf16 g_WhWah[1024 * G4],     g_WhWal[1024 * G4]; // permuted cols
__device__ __align__(16) bf16 g_Wqvh[H_ * H_],        g_Wqvl[H_ * H_];
__device__ __align__(16) bf16 g_Wqxvh[I_ * H_],       g_Wqxvl[I_ * H_];
__device__ __align__(16) bf16 g_HAh[B_ * 1024],       g_HAl[B_ * 1024];

// ---------------- small helpers ---------------------------------------------
__device__ __forceinline__ void split_bf16(float v, bf16* ph, bf16* pl) {
    bf16 h = __float2bfloat16(v);
    *ph = h;
    *pl = __float2bfloat16(v - __bfloat162float(h));
}
__device__ __forceinline__ unsigned smem_u32(const void* p) {
    return (unsigned)__cvta_generic_to_shared(p);
}
__device__ __forceinline__ void ldsm_x4(unsigned addr, unsigned& r0, unsigned& r1,
                                        unsigned& r2, unsigned& r3) {
    asm volatile("ldmatrix.sync.aligned.m8n8.x4.shared.b16 {%0,%1,%2,%3}, [%4];"
                 : "=r"(r0), "=r"(r1), "=r"(r2), "=r"(r3) : "r"(addr));
}
__device__ __forceinline__ void ldsm_x4_t(unsigned addr, unsigned& r0, unsigned& r1,
                                          unsigned& r2, unsigned& r3) {
    asm volatile("ldmatrix.sync.aligned.m8n8.x4.trans.shared.b16 {%0,%1,%2,%3}, [%4];"
                 : "=r"(r0), "=r"(r1), "=r"(r2), "=r"(r3) : "r"(addr));
}
__device__ __forceinline__ void mma16816(float* c, const unsigned* a, unsigned b0, unsigned b1) {
    asm volatile("mma.sync.aligned.m16n8k16.row.col.f32.bf16.bf16.f32 "
                 "{%0,%1,%2,%3}, {%4,%5,%6,%7}, {%8,%9}, {%0,%1,%2,%3};"
                 : "+f"(c[0]), "+f"(c[1]), "+f"(c[2]), "+f"(c[3])
                 : "r"(a[0]), "r"(a[1]), "r"(a[2]), "r"(a[3]), "r"(b0), "r"(b1));
}

#define CP_ASYNC8(s, g) asm volatile("cp.async.ca.shared.global [%0], [%1], 8;" :: "r"(s), "l"(g))
#define CP_COMMIT()     asm volatile("cp.async.commit_group;" ::: "memory")
#define CP_WAIT0()      asm volatile("cp.async.wait_group 0;" ::: "memory")

#define POOL64 36864       // smem bytes for 64x64 gemm (4 x 64x72 bf16)
#define SCAN_SMEM 55296    // CD double-buffered: 2x(32x72)x2 + 2x(64x72)x2 bf16

// ---------------- chunked bf16-split MMA GEMM: 64x64 tile, K-chunk 64 -------
__device__ __forceinline__ void gemm64(
    char* pool,
    const bf16* __restrict__ Ah, const bf16* __restrict__ Al, int lda,
    const bf16* __restrict__ Bh, const bf16* __restrict__ Bl, int ldb,
    float* __restrict__ C, int ldc, const float* __restrict__ bias,
    int m0, int n0, int k0, int nchunk)
{
    bf16* AsH = (bf16*)pool;
    bf16* AsL = (bf16*)(pool + 9216);
    bf16* BsH = (bf16*)(pool + 18432);
    bf16* BsL = (bf16*)(pool + 27648);
    const int tid = threadIdx.x, lane = tid & 31, wid = tid >> 5;
    const int wm = wid & 1, wn = wid >> 1;

    uint2 rA[2][4], rB[2][4];
#define LOADA64(kt) { _Pragma("unroll") for (int j = 0; j < 4; j++) { \
        int u = tid + j * 256, rr = u >> 4, cc = (u & 15) * 4; \
        rA[0][j] = *(const uint2*)&Ah[(size_t)(m0 + rr) * lda + k0 + (kt) * 64 + cc]; \
        rA[1][j] = *(const uint2*)&Al[(size_t)(m0 + rr) * lda + k0 + (kt) * 64 + cc]; } }
#define LOADB64(kt) { _Pragma("unroll") for (int j = 0; j < 4; j++) { \
        int u = tid + j * 256, rr = u >> 4, cc = (u & 15) * 4; \
        rB[0][j] = *(const uint2*)&Bh[(size_t)(k0 + (kt) * 64 + rr) * ldb + n0 + cc]; \
        rB[1][j] = *(const uint2*)&Bl[(size_t)(k0 + (kt) * 64 + rr) * ldb + n0 + cc]; } }

    float acc[2][2][4];
#pragma unroll
    for (int i = 0; i < 2; i++)
#pragma unroll
        for (int j = 0; j < 2; j++)
#pragma unroll
            for (int q = 0; q < 4; q++) acc[i][j][q] = 0.f;

    const int arow = wm * 32 + (lane & 15);
    const int acol = (lane >> 4) * 8;
    const int brow = lane & 15;
    const int bcol = wn * 16 + (lane >> 4) * 8;

    LOADA64(0); LOADB64(0);
    for (int kt = 0; kt < nchunk; kt++) {
        __syncthreads();
#pragma unroll
        for (int j = 0; j < 4; j++) {
            int u = tid + j * 256, rr = u >> 4, cc = (u & 15) * 4;
            *(uint2*)&AsH[rr * 72 + cc] = rA[0][j];
            *(uint2*)&AsL[rr * 72 + cc] = rA[1][j];
            *(uint2*)&BsH[rr * 72 + cc] = rB[0][j];
            *(uint2*)&BsL[rr * 72 + cc] = rB[1][j];
        }
        __syncthreads();
        if (kt + 1 < nchunk) { LOADA64(kt + 1); LOADB64(kt + 1); }
#pragma unroll
        for (int kk = 0; kk < 4; kk++) {
            unsigned aH[2][4], aL[2][4], bH[4], bL[4];
#pragma unroll
            for (int mt = 0; mt < 2; mt++) {
                ldsm_x4(smem_u32(&AsH[(arow + mt * 16) * 72 + acol + kk * 16]),
                        aH[mt][0], aH[mt][1], aH[mt][2], aH[mt][3]);
                ldsm_x4(smem_u32(&AsL[(arow + mt * 16) * 72 + acol + kk * 16]),
                        aL[mt][0], aL[mt][1], aL[mt][2], aL[mt][3]);
            }
            ldsm_x4_t(smem_u32(&BsH[(kk * 16 + brow) * 72 + bcol]), bH[0], bH[1], bH[2], bH[3]);
            ldsm_x4_t(smem_u32(&BsL[(kk * 16 + brow) * 72 + bcol]), bL[0], bL[1], bL[2], bL[3]);
#pragma unroll
            for (int mt = 0; mt < 2; mt++)
#pragma unroll
                for (int nt = 0; nt < 2; nt++) {
                    mma16816(acc[mt][nt], aH[mt], bH[2 * nt], bH[2 * nt + 1]);
                    mma16816(acc[mt][nt], aH[mt], bL[2 * nt], bL[2 * nt + 1]);
                    mma16816(acc[mt][nt], aL[mt], bH[2 * nt], bH[2 * nt + 1]);
                }
        }
    }
#pragma unroll
    for (int mt = 0; mt < 2; mt++)
#pragma unroll
        for (int nt = 0; nt < 2; nt++) {
            int row = m0 + wm * 32 + mt * 16 + (lane >> 2);
            int col = n0 + wn * 16 + nt * 8 + 2 * (lane & 3);
            float bx = 0.f, by = 0.f;
            if (bias) { bx = bias[col]; by = bias[col + 1]; }
            *(float2*)&C[(size_t)row * ldc + col] =
                make_float2(acc[mt][nt][0] + bx, acc[mt][nt][1] + by);
            *(float2*)&C[(size_t)(row + 8) * ldc + col] =
                make_float2(acc[mt][nt][2] + bx, acc[mt][nt][3] + by);
        }
#undef LOADA64
#undef LOADB64
}

// ---------------- fp32 tiled GEMM (one-time weight products) ----------------
__device__ __forceinline__ void gemm_body(
    const float* __restrict__ A, int lda,
    const float* __restrict__ B, int ldb,
    float* __restrict__ C, int ldc,
    int m0, int n0, int nk)
{
    __shared__ float As[2][16][68];
    __shared__ float Bs[2][16][64];
    const int tid = threadIdx.x;
    const int ar = tid >> 2;
    const int ac = (tid & 3) << 2;
    const int br = tid >> 4;
    const int bc = (tid & 15) << 2;
    const float* Aptr = A + (size_t)(m0 + ar) * lda + ac;
    const float* Bptr = B + (size_t)br * ldb + n0 + bc;
    float4 ra = *(const float4*)Aptr;
    float4 rb = *(const float4*)Bptr;
    const int tm = (tid >> 4) << 2;
    const int tn = (tid & 15) << 2;
    float acc[4][4];
#pragma unroll
    for (int i = 0; i < 4; i++)
#pragma unroll
        for (int j = 0; j < 4; j++) acc[i][j] = 0.f;
    int buf = 0;
    for (int kt = 0; kt < nk; kt++) {
        As[buf][ac + 0][ar] = ra.x;
        As[buf][ac + 1][ar] = ra.y;
        As[buf][ac + 2][ar] = ra.z;
        As[buf][ac + 3][ar] = ra.w;
        *(float4*)&Bs[buf][br][bc] = rb;
        __syncthreads();
        if (kt + 1 < nk) {
            ra = *(const float4*)(Aptr + (kt + 1) * 16);
            rb = *(const float4*)(Bptr + (size_t)(kt + 1) * 16 * ldb);
        }
#pragma unroll
        for (int kk = 0; kk < 16; kk++) {
            float4 a = *(const float4*)(&As[buf][kk][tm]);
            float4 b = *(const float4*)(&Bs[buf][kk][tn]);
            acc[0][0] += a.x * b.x; acc[0][1] += a.x * b.y; acc[0][2] += a.x * b.z; acc[0][3] += a.x * b.w;
            acc[1][0] += a.y * b.x; acc[1][1] += a.y * b.y; acc[1][2] += a.y * b.z; acc[1][3] += a.y * b.w;
            acc[2][0] += a.z * b.x; acc[2][1] += a.z * b.y; acc[2][2] += a.z * b.z; acc[2][3] += a.z * b.w;
            acc[3][0] += a.w * b.x; acc[3][1] += a.w * b.y; acc[3][2] += a.w * b.z; acc[3][3] += a.w * b.w;
        }
        buf ^= 1;
    }
#pragma unroll
    for (int i = 0; i < 4; i++) {
        float4 v;
        v.x = acc[i][0]; v.y = acc[i][1]; v.z = acc[i][2]; v.w = acc[i][3];
        *(float4*)&C[(size_t)(m0 + tm + i) * ldc + n0 + tn] = v;
    }
}

// ---------------- precompute ------------------------------------------------
__global__ void k_prep1(const float* __restrict__ Wh, const float* __restrict__ Wv,
                        const float* __restrict__ Wa, const float* __restrict__ bi,
                        const float* __restrict__ ba, const float* __restrict__ bv,
                        const float* __restrict__ Wq, const float* __restrict__ bq)
{
    int idx = blockIdx.x * blockDim.x + threadIdx.x;
    if (idx < 512 * 2048) g_WhWa[idx] = Wh[idx];
    if (idx < 512 * 512) { int r = idx >> 9, c = idx & 511; g_WvT[idx] = Wv[c * 512 + r]; }
    if (idx < W_ * BH) g_Cbuf[idx] = 0.f;
    if (idx < B_ * 1024) { g_HAh[idx] = __float2bfloat16(0.f); g_HAl[idx] = __float2bfloat16(0.f); }
    if (idx < BH) { g_h[idx] = 0.f; g_c[idx] = 0.f; }
    if (idx < G4) {  // permuted bias: idx = 4*channel + gate
        int g = idx & 3, k = idx >> 2;
        int jo = g * 512 + k;
        float s = 0.f;
        for (int k2 = 0; k2 < 512; k2++) s += bv[k2] * Wa[k2 * 2048 + jo];
        g_bia[idx] = bi[jo] + ba[jo] + s;
    }
    if (idx < H_) {
        float s = 0.f, s2 = 0.f;
        for (int k = 0; k < 512; k++) {
            s  += Wq[(128 + idx) * 512 + k] * bv[k];
            s2 += bq[k] * Wv[idx * 512 + k];
        }
        g_wqb[idx] = s; g_bqv[idx] = s2;
    }
    if (idx < I_) {
        float s = 0.f;
        for (int k = 0; k < 512; k++) s += Wq[idx * 512 + k] * bv[k];
        g_u[idx] = s;
    }
    if (idx == 0) {
        float s = 0.f;
        for (int k = 0; k < 512; k++) s += bq[k] * bv[k];
        g_sbq = s;
    }
}

__global__ void k_prep2(const float* __restrict__ Wv, const float* __restrict__ Wa,
                        const float* __restrict__ Wq)
{
    int z = blockIdx.z;
    if (z == 0) {
        gemm_body(Wv, 512, Wa, G4, g_WhWa + 512 * G4, G4,
                  blockIdx.y * 64, blockIdx.x * 64, 32);
    } else if (z == 1) {
        if (blockIdx.x < 8)
            gemm_body(Wq + 128 * 512, 512, g_WvT, 512, g_Wqv, 512,
                      blockIdx.y * 64, blockIdx.x * 64, 32);
    } else {
        if (blockIdx.x < 8 && blockIdx.y < 2)
            gemm_body(Wq, 512, g_WvT, 512, g_Wqxv, 512,
                      blockIdx.y * 64, blockIdx.x * 64, 32);
    }
}

// convert inputs to hi/lo bf16 (Wi columns permuted)
__global__ void k_cvt1(const float* __restrict__ x, const float* __restrict__ Wi)
{
    size_t stride = (size_t)gridDim.x * blockDim.x;
    for (size_t i = blockIdx.x * blockDim.x + threadIdx.x; i < (size_t)TB * I_; i += stride)
        split_bf16(x[i], &g_xh[i], &g_xl[i]);
    for (size_t i = blockIdx.x * blockDim.x + threadIdx.x; i < (size_t)I_ * G4; i += stride) {
        int r = (int)(i >> 11), jp = (int)(i & 2047);
        int jo = (jp & 3) * 512 + (jp >> 2);
        split_bf16(Wi[r * 2048 + jo], &g_Wih[i], &g_Wil[i]);
    }
}
// convert derived weights (WhWa columns permuted)
__global__ void k_cvt2()
{
    size_t stride = (size_t)gridDim.x * blockDim.x;
    for (size_t i = blockIdx.x * blockDim.x + threadIdx.x; i < (size_t)1024 * G4; i += stride) {
        int r = (int)(i >> 11), jp = (int)(i & 2047);
        int jo = (jp & 3) * 512 + (jp >> 2);
        split_bf16(g_WhWa[r * 2048 + jo], &g_WhWah[i], &g_WhWal[i]);
    }
    for (size_t i = blockIdx.x * blockDim.x + threadIdx.x; i < (size_t)H_ * H_; i += stride)
        split_bf16(g_Wqv[i], &g_Wqvh[i], &g_Wqvl[i]);
    for (size_t i = blockIdx.x * blockDim.x + threadIdx.x; i < (size_t)I_ * H_; i += stride)
        split_bf16(g_Wqxv[i], &g_Wqxvh[i], &g_Wqxvl[i]);
}

// big x GEMMs on tensor cores
__global__ void k_xwi(void)
{
    __shared__ __align__(16) char pool[POOL64];
    gemm64(pool, g_xh, g_xl, I_, g_Wih, g_Wil, G4, g_XWi, G4, g_bia,
           blockIdx.y * 64, blockIdx.x * 64, 0, 2);
}
__global__ void k_xqv(void)
{
    __shared__ __align__(16) char pool[POOL64];
    gemm64(pool, g_xh, g_xl, I_, g_Wqxvh, g_Wqxvl, H_, g_XQV, H_, 0,
           blockIdx.y * 64, blockIdx.x * 64, 0, 2);
}

// ---------------- software grid barrier (R10 proven variant) ----------------
__device__ __forceinline__ void gbar(unsigned& ep)
{
    ep++;
    __syncthreads();
    __threadfence();
    if (threadIdx.x == 0) g_flags[blockIdx.x * 32] = ep;
    if (threadIdx.x < NCTA) {
        while (g_flags[threadIdx.x * 32] < ep) __nanosleep(64);
    }
    __threadfence();
    __syncthreads();
}

// ---------------- persistent scan kernel ------------------------------------
__global__ void __launch_bounds__(256, 1)
k_scan(const float* __restrict__ x, float* __restrict__ out)
{
    extern __shared__ __align__(16) char pool[];
    const int bid = blockIdx.x, tid = threadIdx.x;
    const int lane = tid & 31, wid = tid >> 5;
    unsigned ep = g_flags[bid * 32];

    for (int t = 0; t < T_; t++) {
        // ======== Phase A: Qv partials = h @ Wqv (tensor, split-K 8) ========
        if (bid < 128) {
            int s = bid & 7, mt = (bid >> 3) & 1, nt = bid >> 4;
            gemm64(pool, g_HAh, g_HAl, 1024, g_Wqvh, g_Wqvl, H_,
                   g_Qp + (size_t)s * BH, H_, 0,
                   mt * 64, nt * 64, s * 64, 1);
        }
        gbar(ep);

        // ======== Phase B: attention per batch row (fp32) ===================
        if (bid < 128) {
            float* sQv  = (float*)pool;            // 512
            float* sred = (float*)(pool + 2048);   // 256
            float* sp   = (float*)(pool + 3072);   // 16
            const int b = bid;
            const int nv = (t + 1 < W_) ? (t + 1) : W_;
            for (int k = tid; k < H_; k += 256) {
                float q = g_XQV[((size_t)t * B_ + b) * H_ + k] + g_bqv[k];
#pragma unroll
                for (int s = 0; s < 8; s++) q += g_Qp[(size_t)s * BH + b * H_ + k];
                sQv[k] = q;
            }
            float acc = 0.f;
            for (int k = tid; k < H_; k += 256) acc += g_h[b * H_ + k] * g_wqb[k];
            for (int i = tid; i < I_; i += 256) acc += x[((size_t)t * B_ + b) * I_ + i] * g_u[i];
            sred[tid] = acc;
            __syncthreads();
            for (int s = 128; s > 0; s >>= 1) {
                if (tid < s) sred[tid] += sred[tid + s];
                __syncthreads();
            }
            float qb = sred[0] + g_sbq;
            int w = tid >> 4, l = tid & 15;
            float dot = 0.f;
            const float* Cw = g_Cbuf + ((size_t)w * B_ + b) * H_;
            for (int k = l; k < H_; k += 16) dot += sQv[k] * Cw[k];
            dot += __shfl_xor_sync(0xffffffffu, dot, 8);
            dot += __shfl_xor_sync(0xffffffffu, dot, 4);
            dot += __shfl_xor_sync(0xffffffffu, dot, 2);
            dot += __shfl_xor_sync(0xffffffffu, dot, 1);
            if (l == 0) sp[w] = (dot + qb) * INV_SQRT_DK;
            __syncthreads();
            if (tid == 0) {
                float m = -1e30f;
                for (int i = 0; i < nv; i++) m = fmaxf(m, sp[i]);
                float pv[W_]; float d = 0.f;
                for (int i = 0; i < nv; i++) { pv[i] = expf(sp[i] - m); d += pv[i]; }
                float inv = 1.f / d;
                for (int i = 0; i < W_; i++) sp[i] = (i < nv) ? pv[i] * inv : 0.f;
            }
            __syncthreads();
            for (int k = tid; k < H_; k += 256) {
                float a = 0.f;
#pragma unroll
                for (int w2 = 0; w2 < W_; w2++)
                    a += sp[w2] * g_Cbuf[((size_t)w2 * B_ + b) * H_ + k];
                split_bf16(a, &g_HAh[b * 1024 + H_ + k], &g_HAl[b * 1024 + H_ + k]);
            }
        }
        gbar(ep);

        // ======== Phase C+D fused: preact GEMM + cell update ================
        // 128 CTAs: 4 m-tiles (32 rows) x 32 n-tiles (64 perm cols), K=1024
        // cp.async double-buffered mainloop: 1 sync per chunk, loads overlap MMA
        if (bid < 128) {
            const int m0 = (bid & 3) * 32;
            const int n0 = (bid >> 2) * 64;
            const int wm = wid & 1, wn = wid >> 1;

#define ISSUE_CD(kt, sel) { \
    bf16* asH = (bf16*)(pool + (sel) * 4608); \
    bf16* asL = (bf16*)(pool + 9216 + (sel) * 4608); \
    bf16* bsH = (bf16*)(pool + 18432 + (sel) * 9216); \
    bf16* bsL = (bf16*)(pool + 36864 + (sel) * 9216); \
    _Pragma("unroll") for (int j = 0; j < 2; j++) { \
        int u = tid + j * 256, rr = u >> 4, cc = (u & 15) * 4; \
        CP_ASYNC8(smem_u32(&asH[rr * 72 + cc]), &g_HAh[(size_t)(m0 + rr) * 1024 + (kt) * 64 + cc]); \
        CP_ASYNC8(smem_u32(&asL[rr * 72 + cc]), &g_HAl[(size_t)(m0 + rr) * 1024 + (kt) * 64 + cc]); } \
    _Pragma("unroll") for (int j = 0; j < 4; j++) { \
        int u = tid + j * 256, rr = u >> 4, cc = (u & 15) * 4; \
        CP_ASYNC8(smem_u32(&bsH[rr * 72 + cc]), &g_WhWah[(size_t)((kt) * 64 + rr) * G4 + n0 + cc]); \
        CP_ASYNC8(smem_u32(&bsL[rr * 72 + cc]), &g_WhWal[(size_t)((kt) * 64 + rr) * G4 + n0 + cc]); } \
    CP_COMMIT(); }

            float acc[2][4];
#pragma unroll
            for (int i = 0; i < 2; i++)
#pragma unroll
                for (int q = 0; q < 4; q++) acc[i][q] = 0.f;

            const int arow = wm * 16 + (lane & 15);
            const int acol = (lane >> 4) * 8;
            const int brow = lane & 15;
            const int bcol = wn * 16 + (lane >> 4) * 8;

            ISSUE_CD(0, 0);
            for (int kt = 0; kt < 16; kt++) {
                CP_WAIT0();
                __syncthreads();
                if (kt + 1 < 16) ISSUE_CD(kt + 1, (kt + 1) & 1);
                const int sel = kt & 1;
                bf16* AsH = (bf16*)(pool + sel * 4608);
                bf16* AsL = (bf16*)(pool + 9216 + sel * 4608);
                bf16* BsH = (bf16*)(pool + 18432 + sel * 9216);
                bf16* BsL = (bf16*)(pool + 36864 + sel * 9216);
#pragma unroll
                for (int kk = 0; kk < 4; kk++) {
                    unsigned aH[4], aL[4], bH[4], bL[4];
                    ldsm_x4(smem_u32(&AsH[arow * 72 + acol + kk * 16]),
                            aH[0], aH[1], aH[2], aH[3]);
                    ldsm_x4(smem_u32(&AsL[arow * 72 + acol + kk * 16]),
                            aL[0], aL[1], aL[2], aL[3]);
                    ldsm_x4_t(smem_u32(&BsH[(kk * 16 + brow) * 72 + bcol]),
                              bH[0], bH[1], bH[2], bH[3]);
                    ldsm_x4_t(smem_u32(&BsL[(kk * 16 + brow) * 72 + bcol]),
                              bL[0], bL[1], bL[2], bL[3]);
#pragma unroll
                    for (int nt = 0; nt < 2; nt++) {
                        mma16816(acc[nt], aH, bH[2 * nt], bH[2 * nt + 1]);
                        mma16816(acc[nt], aH, bL[2 * nt], bL[2 * nt + 1]);
                        mma16816(acc[nt], aL, bH[2 * nt], bH[2 * nt + 1]);
                    }
                }
            }
#undef ISSUE_CD
            // epilogue: stage preact tile, then fused cell update
            __syncthreads();
            float* spre = (float*)pool;   // 32 x 64
#pragma unroll
            for (int nt = 0; nt < 2; nt++) {
                int row = wm * 16 + (lane >> 2);
                int col = wn * 16 + nt * 8 + 2 * (lane & 3);
                spre[row * 64 + col]       = acc[nt][0];
                spre[row * 64 + col + 1]   = acc[nt][1];
                spre[(row + 8) * 64 + col]     = acc[nt][2];
                spre[(row + 8) * 64 + col + 1] = acc[nt][3];
            }
            __syncthreads();
            const int slot = (t + 1) & (W_ - 1);
#pragma unroll
            for (int i = 0; i < 2; i++) {
                int pair = tid + i * 256;          // 0..511
                int bl = pair >> 4, ch = pair & 15;
                int b = m0 + bl;
                int Kg = (n0 >> 2) + ch;
                float4 pr = *(float4*)&spre[bl * 64 + 4 * ch];
                float4 xw = *(const float4*)&g_XWi[((size_t)t * B_ + b) * G4 + n0 + 4 * ch];
                float pi = pr.x + xw.x, pf = pr.y + xw.y;
                float po = pr.z + xw.z, pg = pr.w + xw.w;
                float ig = 1.f / (1.f + expf(-pi));
                float fg = 1.f / (1.f + expf(-pf));
                float og = 1.f / (1.f + expf(-po));
                float gg = tanhf(pg);
                int idx = b * H_ + Kg;
                float cn = g_c[idx] * fg + ig * gg;
                float hn = og * tanhf(cn);
                g_c[idx] = cn;
                g_h[idx] = hn;
                g_Cbuf[(size_t)slot * BH + idx] = cn;
                split_bf16(hn, &g_HAh[b * 1024 + Kg], &g_HAl[b * 1024 + Kg]);
                out[(size_t)t * BH + idx] = hn;
            }
        }
        gbar(ep);
    }
}

// ---------------- launch ----------------------------------------------------
extern "C" void kernel_launch(void* const* d_in, const int* in_sizes, int n_in,
                              void* d_out, int out_size)
{
    const float* x  = (const float*)d_in[0];
    const float* Wi = (const float*)d_in[1];
    const float* bi = (const float*)d_in[2];
    const float* Wh = (const float*)d_in[3];
    const float* Wv = (const float*)d_in[4];
    const float* bv = (const float*)d_in[5];
    const float* Wq = (const float*)d_in[6];
    const float* bq = (const float*)d_in[7];
    const float* Wa = (const float*)d_in[8];
    const float* ba = (const float*)d_in[9];
    float* out = (float*)d_out;

    cudaFuncSetAttribute(k_scan, cudaFuncAttributeMaxDynamicSharedMemorySize, SCAN_SMEM);

    k_prep1<<<4096, 256>>>(Wh, Wv, Wa, bi, ba, bv, Wq, bq);
    k_cvt1<<<2048, 256>>>(x, Wi);
    k_prep2<<<dim3(32, 8, 3), 256>>>(Wv, Wa, Wq);
    k_cvt2<<<2048, 256>>>();
    k_xwi<<<dim3(32, 256, 1), 256>>>();
    k_xqv<<<dim3(8, 256, 1), 256>>>();
    k_scan<<<NCTA, 256, SCAN_SMEM>>>(x, out);
}

// round 16
// speedup vs baseline: 1.4996x; 1.4996x over previous
#include <cuda_runtime.h>
#include <cuda_bf16.h>
#include <math.h>

#define T_  128
#define B_  128
#define I_  128
#define H_  512
#define W_  16
#define G4  2048
#define BH  65536
#define TB  16384
#define NCTA 148
#define INV_SQRT_DK 0.04419417382415922f

typedef __nv_bfloat16 bf16;

// ---------------- device scratch (static) -----------------------------------
__device__ __align__(16) float g_XWi[(size_t)TB * G4];   // x@Wi_perm + bia_perm (gate-interleaved cols)
__device__ __align__(16) float g_XQV[(size_t)TB * H_];   // x@(Wqx@WvT)
__device__ __align__(16) float g_WhWa[1024 * G4];        // fp32 [Wh ; Wv@Wa] (ORIG col layout)
__device__ __align__(16) float g_Wqv[H_ * H_];           // fp32 Wqh@WvT
__device__ __align__(16) float g_Wqxv[I_ * H_];          // fp32 Wqx@WvT
__device__ __align__(16) float g_WvT[H_ * H_];
__device__ __align__(16) float g_bia[G4];                // permuted
__device__ __align__(16) float g_bqv[H_];
__device__ __align__(16) float g_wqb[H_];
__device__ __align__(16) float g_u[I_];
__device__ float g_sbq;
__device__ __align__(16) float g_h[BH];
__device__ __align__(16) float g_c[BH];
__device__ __align__(16) float g_Cbuf[W_ * BH];
__device__ __align__(16) float g_Qp[8 * BH];
__device__ volatile unsigned g_flags[NCTA * 32];

// hi/lo bf16 split operands
__device__ __align__(16) bf16 g_xh[(size_t)TB * I_],  g_xl[(size_t)TB * I_];
__device__ __align__(16) bf16 g_Wih[I_ * G4],         g_Wil[I_ * G4];     // permuted cols
__device__ __align__(16) bf16 g_WhWah[1024 * G4],     g_WhWal[1024 * G4]; // permuted cols
__device__ __align__(16) bf16 g_Wqvh[H_ * H_],        g_Wqvl[H_ * H_];
__device__ __align__(16) bf16 g_Wqxvh[I_ * H_],       g_Wqxvl[I_ * H_];
__device__ __align__(16) bf16 g_HAh[B_ * 1024],       g_HAl[B_ * 1024];

// ---------------- small helpers ---------------------------------------------
__device__ __forceinline__ void split_bf16(float v, bf16* ph, bf16* pl) {
    bf16 h = __float2bfloat16(v);
    *ph = h;
    *pl = __float2bfloat16(v - __bfloat162float(h));
}
__device__ __forceinline__ unsigned smem_u32(const void* p) {
    return (unsigned)__cvta_generic_to_shared(p);
}
__device__ __forceinline__ void ldsm_x4(unsigned addr, unsigned& r0, unsigned& r1,
                                        unsigned& r2, unsigned& r3) {
    asm volatile("ldmatrix.sync.aligned.m8n8.x4.shared.b16 {%0,%1,%2,%3}, [%4];"
                 : "=r"(r0), "=r"(r1), "=r"(r2), "=r"(r3) : "r"(addr));
}
__device__ __forceinline__ void ldsm_x4_t(unsigned addr, unsigned& r0, unsigned& r1,
                                          unsigned& r2, unsigned& r3) {
    asm volatile("ldmatrix.sync.aligned.m8n8.x4.trans.shared.b16 {%0,%1,%2,%3}, [%4];"
                 : "=r"(r0), "=r"(r1), "=r"(r2), "=r"(r3) : "r"(addr));
}
__device__ __forceinline__ void mma16816(float* c, const unsigned* a, unsigned b0, unsigned b1) {
    asm volatile("mma.sync.aligned.m16n8k16.row.col.f32.bf16.bf16.f32 "
                 "{%0,%1,%2,%3}, {%4,%5,%6,%7}, {%8,%9}, {%0,%1,%2,%3};"
                 : "+f"(c[0]), "+f"(c[1]), "+f"(c[2]), "+f"(c[3])
                 : "r"(a[0]), "r"(a[1]), "r"(a[2]), "r"(a[3]), "r"(b0), "r"(b1));
}

#define POOL64 36864       // smem bytes for 64x64 gemm (4 x 64x72 bf16)
#define SCAN_SMEM 55296    // CD double-buffered: 2x(32x72)x2 + 2x(64x72)x2 bf16

// ---------------- chunked bf16-split MMA GEMM: 64x64 tile, K-chunk 64 -------
// (register-staged, single-buffer; used by phases A and precompute)
__device__ __forceinline__ void gemm64(
    char* pool,
    const bf16* __restrict__ Ah, const bf16* __restrict__ Al, int lda,
    const bf16* __restrict__ Bh, const bf16* __restrict__ Bl, int ldb,
    float* __restrict__ C, int ldc, const float* __restrict__ bias,
    int m0, int n0, int k0, int nchunk)
{
    bf16* AsH = (bf16*)pool;
    bf16* AsL = (bf16*)(pool + 9216);
    bf16* BsH = (bf16*)(pool + 18432);
    bf16* BsL = (bf16*)(pool + 27648);
    const int tid = threadIdx.x, lane = tid & 31, wid = tid >> 5;
    const int wm = wid & 1, wn = wid >> 1;

    uint2 rA[2][4], rB[2][4];
#define LOADA64(kt) { _Pragma("unroll") for (int j = 0; j < 4; j++) { \
        int u = tid + j * 256, rr = u >> 4, cc = (u & 15) * 4; \
        rA[0][j] = *(const uint2*)&Ah[(size_t)(m0 + rr) * lda + k0 + (kt) * 64 + cc]; \
        rA[1][j] = *(const uint2*)&Al[(size_t)(m0 + rr) * lda + k0 + (kt) * 64 + cc]; } }
#define LOADB64(kt) { _Pragma("unroll") for (int j = 0; j < 4; j++) { \
        int u = tid + j * 256, rr = u >> 4, cc = (u & 15) * 4; \
        rB[0][j] = *(const uint2*)&Bh[(size_t)(k0 + (kt) * 64 + rr) * ldb + n0 + cc]; \
        rB[1][j] = *(const uint2*)&Bl[(size_t)(k0 + (kt) * 64 + rr) * ldb + n0 + cc]; } }

    float acc[2][2][4];
#pragma unroll
    for (int i = 0; i < 2; i++)
#pragma unroll
        for (int j = 0; j < 2; j++)
#pragma unroll
            for (int q = 0; q < 4; q++) acc[i][j][q] = 0.f;

    const int arow = wm * 32 + (lane & 15);
    const int acol = (lane >> 4) * 8;
    const int brow = lane & 15;
    const int bcol = wn * 16 + (lane >> 4) * 8;

    LOADA64(0); LOADB64(0);
    for (int kt = 0; kt < nchunk; kt++) {
        __syncthreads();
#pragma unroll
        for (int j = 0; j < 4; j++) {
            int u = tid + j * 256, rr = u >> 4, cc = (u & 15) * 4;
            *(uint2*)&AsH[rr * 72 + cc] = rA[0][j];
            *(uint2*)&AsL[rr * 72 + cc] = rA[1][j];
            *(uint2*)&BsH[rr * 72 + cc] = rB[0][j];
            *(uint2*)&BsL[rr * 72 + cc] = rB[1][j];
        }
        __syncthreads();
        if (kt + 1 < nchunk) { LOADA64(kt + 1); LOADB64(kt + 1); }
#pragma unroll
        for (int kk = 0; kk < 4; kk++) {
            unsigned aH[2][4], aL[2][4], bH[4], bL[4];
#pragma unroll
            for (int mt = 0; mt < 2; mt++) {
                ldsm_x4(smem_u32(&AsH[(arow + mt * 16) * 72 + acol + kk * 16]),
                        aH[mt][0], aH[mt][1], aH[mt][2], aH[mt][3]);
                ldsm_x4(smem_u32(&AsL[(arow + mt * 16) * 72 + acol + kk * 16]),
                        aL[mt][0], aL[mt][1], aL[mt][2], aL[mt][3]);
            }
            ldsm_x4_t(smem_u32(&BsH[(kk * 16 + brow) * 72 + bcol]), bH[0], bH[1], bH[2], bH[3]);
            ldsm_x4_t(smem_u32(&BsL[(kk * 16 + brow) * 72 + bcol]), bL[0], bL[1], bL[2], bL[3]);
#pragma unroll
            for (int mt = 0; mt < 2; mt++)
#pragma unroll
                for (int nt = 0; nt < 2; nt++) {
                    mma16816(acc[mt][nt], aH[mt], bH[2 * nt], bH[2 * nt + 1]);
                    mma16816(acc[mt][nt], aH[mt], bL[2 * nt], bL[2 * nt + 1]);
                    mma16816(acc[mt][nt], aL[mt], bH[2 * nt], bH[2 * nt + 1]);
                }
        }
    }
#pragma unroll
    for (int mt = 0; mt < 2; mt++)
#pragma unroll
        for (int nt = 0; nt < 2; nt++) {
            int row = m0 + wm * 32 + mt * 16 + (lane >> 2);
            int col = n0 + wn * 16 + nt * 8 + 2 * (lane & 3);
            float bx = 0.f, by = 0.f;
            if (bias) { bx = bias[col]; by = bias[col + 1]; }
            *(float2*)&C[(size_t)row * ldc + col] =
                make_float2(acc[mt][nt][0] + bx, acc[mt][nt][1] + by);
            *(float2*)&C[(size_t)(row + 8) * ldc + col] =
                make_float2(acc[mt][nt][2] + bx, acc[mt][nt][3] + by);
        }
#undef LOADA64
#undef LOADB64
}

// ---------------- fp32 tiled GEMM (one-time weight products) ----------------
__device__ __forceinline__ void gemm_body(
    const float* __restrict__ A, int lda,
    const float* __restrict__ B, int ldb,
    float* __restrict__ C, int ldc,
    int m0, int n0, int nk)
{
    __shared__ float As[2][16][68];
    __shared__ float Bs[2][16][64];
    const int tid = threadIdx.x;
    const int ar = tid >> 2;
    const int ac = (tid & 3) << 2;
    const int br = tid >> 4;
    const int bc = (tid & 15) << 2;
    const float* Aptr = A + (size_t)(m0 + ar) * lda + ac;
    const float* Bptr = B + (size_t)br * ldb + n0 + bc;
    float4 ra = *(const float4*)Aptr;
    float4 rb = *(const float4*)Bptr;
    const int tm = (tid >> 4) << 2;
    const int tn = (tid & 15) << 2;
    float acc[4][4];
#pragma unroll
    for (int i = 0; i < 4; i++)
#pragma unroll
        for (int j = 0; j < 4; j++) acc[i][j] = 0.f;
    int buf = 0;
    for (int kt = 0; kt < nk; kt++) {
        As[buf][ac + 0][ar] = ra.x;
        As[buf][ac + 1][ar] = ra.y;
        As[buf][ac + 2][ar] = ra.z;
        As[buf][ac + 3][ar] = ra.w;
        *(float4*)&Bs[buf][br][bc] = rb;
        __syncthreads();
        if (kt + 1 < nk) {
            ra = *(const float4*)(Aptr + (kt + 1) * 16);
            rb = *(const float4*)(Bptr + (size_t)(kt + 1) * 16 * ldb);
        }
#pragma unroll
        for (int kk = 0; kk < 16; kk++) {
            float4 a = *(const float4*)(&As[buf][kk][tm]);
            float4 b = *(const float4*)(&Bs[buf][kk][tn]);
            acc[0][0] += a.x * b.x; acc[0][1] += a.x * b.y; acc[0][2] += a.x * b.z; acc[0][3] += a.x * b.w;
            acc[1][0] += a.y * b.x; acc[1][1] += a.y * b.y; acc[1][2] += a.y * b.z; acc[1][3] += a.y * b.w;
            acc[2][0] += a.z * b.x; acc[2][1] += a.z * b.y; acc[2][2] += a.z * b.z; acc[2][3] += a.z * b.w;
            acc[3][0] += a.w * b.x; acc[3][1] += a.w * b.y; acc[3][2] += a.w * b.z; acc[3][3] += a.w * b.w;
        }
        buf ^= 1;
    }
#pragma unroll
    for (int i = 0; i < 4; i++) {
        float4 v;
        v.x = acc[i][0]; v.y = acc[i][1]; v.z = acc[i][2]; v.w = acc[i][3];
        *(float4*)&C[(size_t)(m0 + tm + i) * ldc + n0 + tn] = v;
    }
}

// ---------------- precompute ------------------------------------------------
__global__ void k_prep1(const float* __restrict__ Wh, const float* __restrict__ Wv,
                        const float* __restrict__ Wa, const float* __restrict__ bi,
                        const float* __restrict__ ba, const float* __restrict__ bv,
                        const float* __restrict__ Wq, const float* __restrict__ bq)
{
    int idx = blockIdx.x * blockDim.x + threadIdx.x;
    if (idx < 512 * 2048) g_WhWa[idx] = Wh[idx];
    if (idx < 512 * 512) { int r = idx >> 9, c = idx & 511; g_WvT[idx] = Wv[c * 512 + r]; }
    if (idx < W_ * BH) g_Cbuf[idx] = 0.f;
    if (idx < B_ * 1024) { g_HAh[idx] = __float2bfloat16(0.f); g_HAl[idx] = __float2bfloat16(0.f); }
    if (idx < BH) { g_h[idx] = 0.f; g_c[idx] = 0.f; }
    if (idx < G4) {  // permuted bias: idx = 4*channel + gate
        int g = idx & 3, k = idx >> 2;
        int jo = g * 512 + k;
        float s = 0.f;
        for (int k2 = 0; k2 < 512; k2++) s += bv[k2] * Wa[k2 * 2048 + jo];
        g_bia[idx] = bi[jo] + ba[jo] + s;
    }
    if (idx < H_) {
        float s = 0.f, s2 = 0.f;
        for (int k = 0; k < 512; k++) {
            s  += Wq[(128 + idx) * 512 + k] * bv[k];
            s2 += bq[k] * Wv[idx * 512 + k];
        }
        g_wqb[idx] = s; g_bqv[idx] = s2;
    }
    if (idx < I_) {
        float s = 0.f;
        for (int k = 0; k < 512; k++) s += Wq[idx * 512 + k] * bv[k];
        g_u[idx] = s;
    }
    if (idx == 0) {
        float s = 0.f;
        for (int k = 0; k < 512; k++) s += bq[k] * bv[k];
        g_sbq = s;
    }
}

__global__ void k_prep2(const float* __restrict__ Wv, const float* __restrict__ Wa,
                        const float* __restrict__ Wq)
{
    int z = blockIdx.z;
    if (z == 0) {
        gemm_body(Wv, 512, Wa, G4, g_WhWa + 512 * G4, G4,
                  blockIdx.y * 64, blockIdx.x * 64, 32);
    } else if (z == 1) {
        if (blockIdx.x < 8)
            gemm_body(Wq + 128 * 512, 512, g_WvT, 512, g_Wqv, 512,
                      blockIdx.y * 64, blockIdx.x * 64, 32);
    } else {
        if (blockIdx.x < 8 && blockIdx.y < 2)
            gemm_body(Wq, 512, g_WvT, 512, g_Wqxv, 512,
                      blockIdx.y * 64, blockIdx.x * 64, 32);
    }
}

// convert inputs to hi/lo bf16 (Wi columns permuted)
__global__ void k_cvt1(const float* __restrict__ x, const float* __restrict__ Wi)
{
    size_t stride = (size_t)gridDim.x * blockDim.x;
    for (size_t i = blockIdx.x * blockDim.x + threadIdx.x; i < (size_t)TB * I_; i += stride)
        split_bf16(x[i], &g_xh[i], &g_xl[i]);
    for (size_t i = blockIdx.x * blockDim.x + threadIdx.x; i < (size_t)I_ * G4; i += stride) {
        int r = (int)(i >> 11), jp = (int)(i & 2047);
        int jo = (jp & 3) * 512 + (jp >> 2);
        split_bf16(Wi[r * 2048 + jo], &g_Wih[i], &g_Wil[i]);
    }
}
// convert derived weights (WhWa columns permuted)
__global__ void k_cvt2()
{
    size_t stride = (size_t)gridDim.x * blockDim.x;
    for (size_t i = blockIdx.x * blockDim.x + threadIdx.x; i < (size_t)1024 * G4; i += stride) {
        int r = (int)(i >> 11), jp = (int)(i & 2047);
        int jo = (jp & 3) * 512 + (jp >> 2);
        split_bf16(g_WhWa[r * 2048 + jo], &g_WhWah[i], &g_WhWal[i]);
    }
    for (size_t i = blockIdx.x * blockDim.x + threadIdx.x; i < (size_t)H_ * H_; i += stride)
        split_bf16(g_Wqv[i], &g_Wqvh[i], &g_Wqvl[i]);
    for (size_t i = blockIdx.x * blockDim.x + threadIdx.x; i < (size_t)I_ * H_; i += stride)
        split_bf16(g_Wqxv[i], &g_Wqxvh[i], &g_Wqxvl[i]);
}

// big x GEMMs on tensor cores
__global__ void k_xwi(void)
{
    __shared__ __align__(16) char pool[POOL64];
    gemm64(pool, g_xh, g_xl, I_, g_Wih, g_Wil, G4, g_XWi, G4, g_bia,
           blockIdx.y * 64, blockIdx.x * 64, 0, 2);
}
__global__ void k_xqv(void)
{
    __shared__ __align__(16) char pool[POOL64];
    gemm64(pool, g_xh, g_xl, I_, g_Wqxvh, g_Wqxvl, H_, g_XQV, H_, 0,
           blockIdx.y * 64, blockIdx.x * 64, 0, 2);
}

// ---------------- software grid barrier (R10 proven variant) ----------------
__device__ __forceinline__ void gbar(unsigned& ep)
{
    ep++;
    __syncthreads();
    __threadfence();
    if (threadIdx.x == 0) g_flags[blockIdx.x * 32] = ep;
    if (threadIdx.x < NCTA) {
        while (g_flags[threadIdx.x * 32] < ep) __nanosleep(64);
    }
    __threadfence();
    __syncthreads();
}

// ---------------- persistent scan kernel ------------------------------------
__global__ void __launch_bounds__(256, 1)
k_scan(const float* __restrict__ x, float* __restrict__ out)
{
    extern __shared__ __align__(16) char pool[];
    const int bid = blockIdx.x, tid = threadIdx.x;
    const int lane = tid & 31, wid = tid >> 5;
    unsigned ep = g_flags[bid * 32];

    for (int t = 0; t < T_; t++) {
        // ======== Phase A: Qv partials = h @ Wqv (tensor, split-K 8) ========
        if (bid < 128) {
            int s = bid & 7, mt = (bid >> 3) & 1, nt = bid >> 4;
            gemm64(pool, g_HAh, g_HAl, 1024, g_Wqvh, g_Wqvl, H_,
                   g_Qp + (size_t)s * BH, H_, 0,
                   mt * 64, nt * 64, s * 64, 1);
        }
        gbar(ep);

        // ======== Phase B: attention per batch row (fp32) ===================
        if (bid < 128) {
            float* sQv  = (float*)pool;            // 512
            float* sred = (float*)(pool + 2048);   // 256
            float* sp   = (float*)(pool + 3072);   // 16
            const int b = bid;
            const int nv = (t + 1 < W_) ? (t + 1) : W_;
            for (int k = tid; k < H_; k += 256) {
                float q = g_XQV[((size_t)t * B_ + b) * H_ + k] + g_bqv[k];
#pragma unroll
                for (int s = 0; s < 8; s++) q += g_Qp[(size_t)s * BH + b * H_ + k];
                sQv[k] = q;
            }
            float acc = 0.f;
            for (int k = tid; k < H_; k += 256) acc += g_h[b * H_ + k] * g_wqb[k];
            for (int i = tid; i < I_; i += 256) acc += x[((size_t)t * B_ + b) * I_ + i] * g_u[i];
            sred[tid] = acc;
            __syncthreads();
            for (int s = 128; s > 0; s >>= 1) {
                if (tid < s) sred[tid] += sred[tid + s];
                __syncthreads();
            }
            float qb = sred[0] + g_sbq;
            int w = tid >> 4, l = tid & 15;
            float dot = 0.f;
            const float* Cw = g_Cbuf + ((size_t)w * B_ + b) * H_;
            for (int k = l; k < H_; k += 16) dot += sQv[k] * Cw[k];
            dot += __shfl_xor_sync(0xffffffffu, dot, 8);
            dot += __shfl_xor_sync(0xffffffffu, dot, 4);
            dot += __shfl_xor_sync(0xffffffffu, dot, 2);
            dot += __shfl_xor_sync(0xffffffffu, dot, 1);
            if (l == 0) sp[w] = (dot + qb) * INV_SQRT_DK;
            __syncthreads();
            if (tid == 0) {
                float m = -1e30f;
                for (int i = 0; i < nv; i++) m = fmaxf(m, sp[i]);
                float pv[W_]; float d = 0.f;
                for (int i = 0; i < nv; i++) { pv[i] = expf(sp[i] - m); d += pv[i]; }
                float inv = 1.f / d;
                for (int i = 0; i < W_; i++) sp[i] = (i < nv) ? pv[i] * inv : 0.f;
            }
            __syncthreads();
            for (int k = tid; k < H_; k += 256) {
                float a = 0.f;
#pragma unroll
                for (int w2 = 0; w2 < W_; w2++)
                    a += sp[w2] * g_Cbuf[((size_t)w2 * B_ + b) * H_ + k];
                split_bf16(a, &g_HAh[b * 1024 + H_ + k], &g_HAl[b * 1024 + H_ + k]);
            }
        }
        gbar(ep);

        // ======== Phase C+D fused: preact GEMM + cell update ================
        // 128 CTAs: 4 m-tiles (32 rows) x 32 n-tiles (64 perm cols), K=1024
        // Register-staged + DOUBLE-BUFFERED smem: ONE sync per chunk.
        if (bid < 128) {
            const int m0 = (bid & 3) * 32;
            const int n0 = (bid >> 2) * 64;
            const int wm = wid & 1, wn = wid >> 1;

            uint2 rA[2][2], rB[2][4];
#define LOADA_CD(kt) { _Pragma("unroll") for (int j = 0; j < 2; j++) { \
        int u = tid + j * 256, rr = u >> 4, cc = (u & 15) * 4; \
        rA[0][j] = *(const uint2*)&g_HAh[(size_t)(m0 + rr) * 1024 + (kt) * 64 + cc]; \
        rA[1][j] = *(const uint2*)&g_HAl[(size_t)(m0 + rr) * 1024 + (kt) * 64 + cc]; } }
#define LOADB_CD(kt) { _Pragma("unroll") for (int j = 0; j < 4; j++) { \
        int u = tid + j * 256, rr = u >> 4, cc = (u & 15) * 4; \
        rB[0][j] = *(const uint2*)&g_WhWah[(size_t)((kt) * 64 + rr) * G4 + n0 + cc]; \
        rB[1][j] = *(const uint2*)&g_WhWal[(size_t)((kt) * 64 + rr) * G4 + n0 + cc]; } }

            float acc[2][4];
#pragma unroll
            for (int i = 0; i < 2; i++)
#pragma unroll
                for (int q = 0; q < 4; q++) acc[i][q] = 0.f;

            const int arow = wm * 16 + (lane & 15);
            const int acol = (lane >> 4) * 8;
            const int brow = lane & 15;
            const int bcol = wn * 16 + (lane >> 4) * 8;

            LOADA_CD(0); LOADB_CD(0);
            for (int kt = 0; kt < 16; kt++) {
                const int sel = kt & 1;
                bf16* AsH = (bf16*)(pool + sel * 4608);
                bf16* AsL = (bf16*)(pool + 9216 + sel * 4608);
                bf16* BsH = (bf16*)(pool + 18432 + sel * 9216);
                bf16* BsL = (bf16*)(pool + 36864 + sel * 9216);
#pragma unroll
                for (int j = 0; j < 2; j++) {
                    int u = tid + j * 256, rr = u >> 4, cc = (u & 15) * 4;
                    *(uint2*)&AsH[rr * 72 + cc] = rA[0][j];
                    *(uint2*)&AsL[rr * 72 + cc] = rA[1][j];
                }
#pragma unroll
                for (int j = 0; j < 4; j++) {
                    int u = tid + j * 256, rr = u >> 4, cc = (u & 15) * 4;
                    *(uint2*)&BsH[rr * 72 + cc] = rB[0][j];
                    *(uint2*)&BsL[rr * 72 + cc] = rB[1][j];
                }
                __syncthreads();
                if (kt + 1 < 16) { LOADA_CD(kt + 1); LOADB_CD(kt + 1); }
#pragma unroll
                for (int kk = 0; kk < 4; kk++) {
                    unsigned aH[4], aL[4], bH[4], bL[4];
                    ldsm_x4(smem_u32(&AsH[arow * 72 + acol + kk * 16]),
                            aH[0], aH[1], aH[2], aH[3]);
                    ldsm_x4(smem_u32(&AsL[arow * 72 + acol + kk * 16]),
                            aL[0], aL[1], aL[2], aL[3]);
                    ldsm_x4_t(smem_u32(&BsH[(kk * 16 + brow) * 72 + bcol]),
                              bH[0], bH[1], bH[2], bH[3]);
                    ldsm_x4_t(smem_u32(&BsL[(kk * 16 + brow) * 72 + bcol]),
                              bL[0], bL[1], bL[2], bL[3]);
#pragma unroll
                    for (int nt = 0; nt < 2; nt++) {
                        mma16816(acc[nt], aH, bH[2 * nt], bH[2 * nt + 1]);
                        mma16816(acc[nt], aH, bL[2 * nt], bL[2 * nt + 1]);
                        mma16816(acc[nt], aL, bH[2 * nt], bH[2 * nt + 1]);
                    }
                }
            }
#undef LOADA_CD
#undef LOADB_CD
            // epilogue: stage preact tile, then fused cell update
            __syncthreads();
            float* spre = (float*)pool;   // 32 x 64
#pragma unroll
            for (int nt = 0; nt < 2; nt++) {
                int row = wm * 16 + (lane >> 2);
                int col = wn * 16 + nt * 8 + 2 * (lane & 3);
                spre[row * 64 + col]       = acc[nt][0];
                spre[row * 64 + col + 1]   = acc[nt][1];
                spre[(row + 8) * 64 + col]     = acc[nt][2];
                spre[(row + 8) * 64 + col + 1] = acc[nt][3];
            }
            __syncthreads();
            const int slot = (t + 1) & (W_ - 1);
#pragma unroll
            for (int i = 0; i < 2; i++) {
                int pair = tid + i * 256;          // 0..511
                int bl = pair >> 4, ch = pair & 15;
                int b = m0 + bl;
                int Kg = (n0 >> 2) + ch;
                float4 pr = *(float4*)&spre[bl * 64 + 4 * ch];
                float4 xw = *(const float4*)&g_XWi[((size_t)t * B_ + b) * G4 + n0 + 4 * ch];
                float pi = pr.x + xw.x, pf = pr.y + xw.y;
                float po = pr.z + xw.z, pg = pr.w + xw.w;
                float ig = 1.f / (1.f + expf(-pi));
                float fg = 1.f / (1.f + expf(-pf));
                float og = 1.f / (1.f + expf(-po));
                float gg = tanhf(pg);
                int idx = b * H_ + Kg;
                float cn = g_c[idx] * fg + ig * gg;
                float hn = og * tanhf(cn);
                g_c[idx] = cn;
                g_h[idx] = hn;
                g_Cbuf[(size_t)slot * BH + idx] = cn;
                split_bf16(hn, &g_HAh[b * 1024 + Kg], &g_HAl[b * 1024 + Kg]);
                out[(size_t)t * BH + idx] = hn;
            }
        }
        gbar(ep);
    }
}

// ---------------- launch ----------------------------------------------------
extern "C" void kernel_launch(void* const* d_in, const int* in_sizes, int n_in,
                              void* d_out, int out_size)
{
    const float* x  = (const float*)d_in[0];
    const float* Wi = (const float*)d_in[1];
    const float* bi = (const float*)d_in[2];
    const float* Wh = (const float*)d_in[3];
    const float* Wv = (const float*)d_in[4];
    const float* bv = (const float*)d_in[5];
    const float* Wq = (const float*)d_in[6];
    const float* bq = (const float*)d_in[7];
    const float* Wa = (const float*)d_in[8];
    const float* ba = (const float*)d_in[9];
    float* out = (float*)d_out;

    cudaFuncSetAttribute(k_scan, cudaFuncAttributeMaxDynamicSharedMemorySize, SCAN_SMEM);

    k_prep1<<<4096, 256>>>(Wh, Wv, Wa, bi, ba, bv, Wq, bq);
    k_cvt1<<<2048, 256>>>(x, Wi);
    k_prep2<<<dim3(32, 8, 3), 256>>>(Wv, Wa, Wq);
    k_cvt2<<<2048, 256>>>();
    k_xwi<<<dim3(32, 256, 1), 256>>>();
    k_xqv<<<dim3(8, 256, 1), 256>>>();
    k_scan<<<NCTA, 256, SCAN_SMEM>>>(x, out);
}